// round 16
// baseline (speedup 1.0000x reference)
#include <cuda_runtime.h>
#include <cuda_fp16.h>

#define NB 64
#define NC 64
#define NH 32
#define NW 32
#define NOC 128
#define NL 1024
#define PH 34
#define NCTA2 256                     // grid for GEMM

#define A_PIX_B 3072                  // 64 b-rows x 48 B (16ch fp16 + pad)
#define A_STG_B (2 * A_PIX_B)         // 6144 B (2 pixels)
#define WST 268                       // W smem row stride (floats) -> conflict-free
#define W_STG_B (16 * WST * 4)        // 17152 B (16 ch-rows x 1KB data + pad)
#define STG_B (A_STG_B + W_STG_B)     // 23296 B
#define NSTG 4
#define MBAR_OFF (NSTG * STG_B)       // 93184
#define SMEM_BYTES (MBAR_OFF + 64)    // x2 CTAs = 186.5 KB

// Scratch: x as fp16, [pixel=(y*34+x)][b][c], border zero.
__device__ __half g_xh[PH * PH * NB * NC];

// ---------------------------------------------------------------------------
__device__ __forceinline__ void cp16(unsigned int s, const void* g) {
    asm volatile("cp.async.cg.shared.global [%0], [%1], 16;" :: "r"(s), "l"(g));
}
__device__ __forceinline__ unsigned int pack_h2(float a, float b) {
    __half2 h = __floats2half2_rn(a, b);
    return *reinterpret_cast<unsigned int*>(&h);
}
__device__ __forceinline__ void mbar_init(unsigned int a, unsigned int c) {
    asm volatile("mbarrier.init.shared.b64 [%0], %1;" :: "r"(a), "r"(c) : "memory");
}
__device__ __forceinline__ void mbar_arrive(unsigned int a) {
    asm volatile("mbarrier.arrive.shared.b64 _, [%0];" :: "r"(a) : "memory");
}
__device__ __forceinline__ void mbar_wait(unsigned int a, int par) {
    asm volatile(
        "{\n\t.reg .pred P;\n\tW%=:\n\t"
        "mbarrier.try_wait.parity.shared.b64 P, [%0], %1;\n\t"
        "@!P bra W%=;\n\t}" :: "r"(a), "r"(par) : "memory");
}

// ---------------------------------------------------------------------------
// Kernel 0: zero border pixels of g_xh. grid 132 x 128.
// ---------------------------------------------------------------------------
__global__ void __launch_bounds__(128) border_kernel() {
    int bp = blockIdx.x, y, xx;
    if (bp < PH)               { y = 0;       xx = bp; }
    else if (bp < 2 * PH)      { y = PH - 1;  xx = bp - PH; }
    else if (bp < 2 * PH + NH) { y = bp - 2 * PH + 1; xx = 0; }
    else                       { y = bp - (2 * PH + NH) + 1; xx = PH - 1; }
    uint4* dst = (uint4*)(g_xh + (size_t)(y * PH + xx) * (NB * NC));
    #pragma unroll
    for (int i = 0; i < 4; ++i)
        dst[threadIdx.x + i * 128] = make_uint4(0, 0, 0, 0);
}

// ---------------------------------------------------------------------------
// Kernel 1: x[b][c][h][w] f32 -> g_xh[(h+1)*34+(w+1)][b][c] fp16.
// grid (32 h, 8 b-groups), 256 thr.  (R8-proven)
// ---------------------------------------------------------------------------
__global__ void __launch_bounds__(256) transpose_half_kernel(const float* __restrict__ x) {
    __shared__ __half s[8][64][33];
    int h = blockIdx.x;
    int b0 = blockIdx.y * 8;
    int tid = threadIdx.x;
    for (int idx = tid; idx < 8 * 64 * 32; idx += 256) {
        int b = idx >> 11, c = (idx >> 5) & 63, w = idx & 31;
        float v = x[(((size_t)(b0 + b) * NC + c) * NH + h) * NW + w];
        s[b][c][w] = __float2half_rn(v);
    }
    __syncthreads();
    for (int idx = tid; idx < 32 * 8 * 64; idx += 256) {
        int w = idx >> 9, b = (idx >> 6) & 7, c = idx & 63;
        g_xh[((size_t)((h + 1) * PH + (w + 1)) * NB + (b0 + b)) * NC + c] = s[b][c][w];
    }
}

// ---------------------------------------------------------------------------
// Kernel 2: warp-specialized GEMM over location PAIRS (1KB W bursts).
// 320 thr: warps 0-7 consumers (loc = wid&1, Mhalf = (wid>>1)&1, OChalf =
// wid>>2; each M=32 x OC=64), warps 8-9 producers. 4-stage ring, lag-2.
// Each CTA: pairs {cta, cta+256}, 36 segs (9 taps x 4 ch-quarters) per pair.
// ---------------------------------------------------------------------------
__global__ void __launch_bounds__(320, 2) lc_kernel(
    const float* __restrict__ w, const float* __restrict__ bias,
    float* __restrict__ out)
{
    extern __shared__ unsigned char smp[];
    unsigned int sbase = (unsigned int)__cvta_generic_to_shared(smp);
    int tid = threadIdx.x, lane = tid & 31, wid = tid >> 5;
    int cta = blockIdx.x;

    if (tid == 0) {
        #pragma unroll
        for (int s = 0; s < NSTG; ++s) {
            mbar_init(sbase + MBAR_OFF + s * 16, 2);      // full: 2 producer warps
            mbar_init(sbase + MBAR_OFF + s * 16 + 8, 8);  // empty: 8 consumer warps
        }
    }
    __syncthreads();

    const int G = 72;                  // 2 pairs x 36 segments

    if (wid >= 8) {
        // ===================== PRODUCERS (2 warps) =====================
        int ptid = tid - 256;          // 0..63
        for (int g = 0; g < G; ++g) {
            int s = g & 3;
            mbar_wait(sbase + MBAR_OFF + s * 16 + 8, ((g >> 2) & 1) ^ 1);
            asm volatile("fence.proxy.async.shared::cta;" ::: "memory");
            int pp = (g >= 36);
            int seg = g - 36 * pp;
            int tap = seg >> 2, c0 = (seg & 3) << 4;
            int l = 2 * (cta + 256 * pp);
            int pixbase = ((l >> 5) + tap / 3) * PH + (l & 31) + tap % 3;
            unsigned int aS = sbase + (unsigned)(s * STG_B);
            unsigned int wS = aS + A_STG_B;
            // A: 2 pixels x 64 b-rows x 32 B (ch c0..c0+15)
            const char* xs = (const char*)g_xh + (size_t)pixbase * 8192 + c0 * 2;
            #pragma unroll
            for (int f = 0; f < 4; ++f) {
                int idx = ptid + f * 64;
                int p = idx >> 7, b = (idx >> 1) & 63, j = idx & 1;
                cp16(aS + (unsigned)(p * A_PIX_B + b * 48 + j * 16),
                     xs + (size_t)p * 8192 + b * 128 + j * 16);
            }
            // W: 16 ch-rows x 1024 B (2 consecutive locations contiguous)
            #pragma unroll
            for (int f = 0; f < 16; ++f) {
                int idx = ptid + f * 64;
                int r = idx >> 6, j = idx & 63;
                cp16(wS + (unsigned)(r * (WST * 4) + j * 16),
                     (const char*)w
                     + (((size_t)((c0 + r) * 9 + tap) * NL + l) * NOC) * 4 + j * 16);
            }
            asm volatile("cp.async.commit_group;" ::: "memory");
            if (g >= 2) {
                asm volatile("cp.async.wait_group 2;" ::: "memory");
                if (lane == 0) mbar_arrive(sbase + MBAR_OFF + ((g - 2) & 3) * 16);
            }
        }
        asm volatile("cp.async.wait_group 1;" ::: "memory");
        if (lane == 0) mbar_arrive(sbase + MBAR_OFF + ((G - 2) & 3) * 16);
        asm volatile("cp.async.wait_group 0;" ::: "memory");
        if (lane == 0) mbar_arrive(sbase + MBAR_OFF + ((G - 1) & 3) * 16);
    } else {
        // ===================== CONSUMERS (8 warps) =====================
        int loc = wid & 1;
        int mb = ((wid >> 1) & 1) * 32;     // M half base
        int ob = (wid >> 2) * 64;           // OC half base
        float acc[2][8][4];
        for (int g = 0; g < G; ++g) {
            int s = g & 3;
            int pp = (g >= 36);
            int seg = g - 36 * pp;
            if (seg == 0) {
                #pragma unroll
                for (int mt = 0; mt < 2; ++mt)
                    #pragma unroll
                    for (int nt = 0; nt < 8; ++nt)
                        #pragma unroll
                        for (int qq = 0; qq < 4; ++qq) acc[mt][nt][qq] = 0.f;
            }
            mbar_wait(sbase + MBAR_OFF + s * 16, (g >> 2) & 1);

            unsigned int aS = sbase + (unsigned)(s * STG_B + loc * A_PIX_B);
            const float* Bs = (const float*)(smp + s * STG_B + A_STG_B);
            unsigned int a[2][4], bh[8][2];
            #pragma unroll
            for (int mt = 0; mt < 2; ++mt) {
                unsigned int addr = aS + (unsigned)(
                    (mb + mt * 16 + (lane & 15)) * 48 + ((lane >> 4) << 4));
                asm volatile("ldmatrix.sync.aligned.m8n8.x4.shared.b16 "
                             "{%0,%1,%2,%3}, [%4];"
                             : "=r"(a[mt][0]), "=r"(a[mt][1]),
                               "=r"(a[mt][2]), "=r"(a[mt][3])
                             : "r"(addr));
            }
            int k0 = (lane & 3) * 2;
            int colb = loc * 128 + ob + (lane >> 2);
            #pragma unroll
            for (int nt = 0; nt < 8; ++nt) {
                int col = colb + nt * 8;
                bh[nt][0] = pack_h2(Bs[k0 * WST + col], Bs[(k0 + 1) * WST + col]);
                bh[nt][1] = pack_h2(Bs[(k0 + 8) * WST + col], Bs[(k0 + 9) * WST + col]);
            }
            #pragma unroll
            for (int mt = 0; mt < 2; ++mt)
                #pragma unroll
                for (int nt = 0; nt < 8; ++nt) {
                    asm volatile(
                        "mma.sync.aligned.m16n8k16.row.col.f32.f16.f16.f32 "
                        "{%0,%1,%2,%3}, {%4,%5,%6,%7}, {%8,%9}, {%0,%1,%2,%3};"
                        : "+f"(acc[mt][nt][0]), "+f"(acc[mt][nt][1]),
                          "+f"(acc[mt][nt][2]), "+f"(acc[mt][nt][3])
                        : "r"(a[mt][0]), "r"(a[mt][1]), "r"(a[mt][2]), "r"(a[mt][3]),
                          "r"(bh[nt][0]), "r"(bh[nt][1]));
                }
            if (lane == 0) mbar_arrive(sbase + MBAR_OFF + s * 16 + 8);

            if (seg == 35) {
                int l = 2 * (cta + 256 * pp) + loc;
                #pragma unroll
                for (int mt = 0; mt < 2; ++mt) {
                    int r0 = mb + mt * 16 + (lane >> 2);
                    #pragma unroll
                    for (int nt = 0; nt < 8; ++nt) {
                        int c0o = ob + nt * 8 + 2 * (lane & 3);
                        float bz0 = bias[(size_t)c0o * NL + l];
                        float bz1 = bias[(size_t)(c0o + 1) * NL + l];
                        float* p = out + (size_t)r0 * (NOC * NL) + (size_t)c0o * NL + l;
                        p[0]                         = acc[mt][nt][0] + bz0;
                        p[NL]                        = acc[mt][nt][1] + bz1;
                        p[(size_t)8 * NOC * NL]      = acc[mt][nt][2] + bz0;
                        p[(size_t)8 * NOC * NL + NL] = acc[mt][nt][3] + bz1;
                    }
                }
            }
        }
    }
}

// ---------------------------------------------------------------------------
extern "C" void kernel_launch(void* const* d_in, const int* in_sizes, int n_in,
                              void* d_out, int out_size) {
    const float* x    = (const float*)d_in[0];   // (64,64,32,32)
    const float* wgt  = (const float*)d_in[1];   // (1,576,1024,128)
    const float* bias = (const float*)d_in[2];   // (1,128,32,32)
    float* out = (float*)d_out;                  // (64,128,32,32)

    cudaFuncSetAttribute(lc_kernel,
                         cudaFuncAttributeMaxDynamicSharedMemorySize, SMEM_BYTES);

    border_kernel<<<132, 128>>>();
    transpose_half_kernel<<<dim3(NH, 8), 256>>>(x);
    lc_kernel<<<NCTA2, 320, SMEM_BYTES>>>(wgt, bias, out);
}